// round 7
// baseline (speedup 1.0000x reference)
#include <cuda_runtime.h>
#include <cuda_bf16.h>

// Problem constants
// z:   [32, 256, 32, 32] float32   (B, C, H, W)
// emb: [1024, 256] float32         (K, C)
// out: [8388608 z_q_st][32768 indices-as-f32][1 loss]  (float32)

#define BQ      32
#define CQ      256
#define HWQ     1024          // H*W
#define NPX     32768         // B*H*W
#define KQ      1024
#define ZQ_ELEMS 8388608      // B*C*H*W

typedef unsigned long long u64;

// Scratch (no allocations allowed)
__device__ float g_en2[KQ];
__device__ float g_zn2[NPX];
__device__ int   g_idx[NPX];
__device__ float g_part[8192];

// ---------------------------------------------------------------------------
// Kernel 1: ||e_k||^2 per code. Magnitude ~8e-5; its last-ulp order noise is
// ~3e-7 grid units at the fl(zn2+en2) rounding -> argmin-irrelevant.
// ---------------------------------------------------------------------------
__global__ void vq_en2(const float* __restrict__ emb) {
    int warp = (blockIdx.x * blockDim.x + threadIdx.x) >> 5;   // 0..63
    int lane = threadIdx.x & 31;
    for (int i = 0; i < 16; i++) {
        int k = warp * 16 + i;
        const float* row = emb + (long)k * CQ;
        float s = 0.0f;
        #pragma unroll
        for (int j = 0; j < 8; j++) {
            float v = row[lane + 32 * j];
            s = __fadd_rn(s, __fmul_rn(v, v));
        }
        #pragma unroll
        for (int off = 16; off; off >>= 1)
            s = __fadd_rn(s, __shfl_xor_sync(0xffffffffu, s, off));
        if (lane == 0) g_en2[k] = s;
    }
}

// ---------------------------------------------------------------------------
// Kernel 1b: ||z_n||^2 per pixel. NOTE (R5 lesson): zn2 rounding shifts a
// pixel's whole distance row uniformly -> argmin-invariant. Any order works.
// Warp per pixel, strided-c reads.
// ---------------------------------------------------------------------------
__global__ void vq_zn2(const float* __restrict__ z) {
    int n = blockIdx.x * 8 + (threadIdx.x >> 5);   // warp per pixel
    int lane = threadIdx.x & 31;
    int bb = n >> 10;
    int hw = n & 1023;
    const float* p = z + ((long)bb << 18) + hw;
    float s = 0.0f;
    #pragma unroll
    for (int j = 0; j < 8; j++) {
        float v = p[(long)(lane + 32 * j) * HWQ];
        s = __fadd_rn(s, __fmul_rn(v, v));
    }
    #pragma unroll
    for (int off = 16; off; off >>= 1)
        s = __fadd_rn(s, __shfl_xor_sync(0xffffffffu, s, off));
    if (lane == 0) g_zn2[n] = s;
}

// ---------------------------------------------------------------------------
// Kernel 2: fused distance-GEMM + argmin.  H2 TEST: exact fp32 inputs
// (NO tf32 rounding), fp32 sequential-k fma accumulation.
// Final distance replicates reference fp32 rounding:
//   d = fl( fl(zn2 + en2) - fl(2*dot) );  ties -> lowest index.
// Block tile: 64 pixels x full K; thread tile 8px x 8codes via f32x2 FMA.
// ---------------------------------------------------------------------------
#define ZS_STRIDE 68     // 64 + pad
#define ES_STRIDE 264    // 256 + pad
#define SMEM_BYTES ((64 * ZS_STRIDE + 64 * ES_STRIDE) * 4)   // 84992 B

__global__ void __launch_bounds__(256, 2)
vq_argmin(const float* __restrict__ z, const float* __restrict__ emb,
          float* __restrict__ out_idx_f) {
    extern __shared__ float smem[];
    float* zs = smem;                       // [64][ZS_STRIDE]  z-tile, c-major
    float* es = smem + 64 * ZS_STRIDE;      // [64][ES_STRIDE]  e-tile, c-major

    const int t  = threadIdx.x;
    const int pg = t & 7;         // pixel group
    const int kg = t >> 3;        // code group (0..31)
    const int blk = blockIdx.x;
    const int bb  = blk >> 4;                    // batch
    const int hw0 = (blk & 15) << 6;             // 64-pixel offset within HW
    const float* zbase = z + ((long)bb << 18) + hw0;   // bb*C*HW

    const int pxA = pg * 4;        // pixels pxA..pxA+3
    const int pxB = 32 + pg * 4;   // pixels pxB..pxB+3  (split avoids bank alias)
    const int k0  = kg * 8;

    // per-pixel ||z||^2
    float zn2p[8];
    #pragma unroll
    for (int j = 0; j < 8; j++) {
        int px = (j < 4) ? (pxA + j) : (pxB + j - 4);
        zn2p[j] = g_zn2[blk * 64 + px];
    }

    float bestv[8];
    int   besti[8];
    #pragma unroll
    for (int i = 0; i < 8; i++) { bestv[i] = 3.402823466e38f; besti[i] = 0x7fffffff; }

    for (int kb = 0; kb < KQ; kb += 256) {
        u64 acc[4][8];
        #pragma unroll
        for (int pp = 0; pp < 4; pp++)
            #pragma unroll
            for (int k = 0; k < 8; k++) acc[pp][k] = 0ull;

        for (int ct = 0; ct < CQ; ct += 64) {
            __syncthreads();
            // ---- z-tile: zs[c][p] = z[bb, ct+c, hw0+p]  (exact fp32)
            {
                int c = t >> 2;
                int q = (t & 3) << 4;
                const float4* src = (const float4*)(zbase + (long)(ct + c) * HWQ + q);
                float4 v0 = src[0], v1 = src[1], v2 = src[2], v3 = src[3];
                float* d = zs + c * ZS_STRIDE + q;
                *(float4*)(d)      = v0;
                *(float4*)(d + 4)  = v1;
                *(float4*)(d + 8)  = v2;
                *(float4*)(d + 12) = v3;
            }
            // ---- e-tile transposed: es[c][k] = emb[kb+k][ct+c]  (exact fp32)
            {
                const float4* er = (const float4*)(emb + ((long)(kb + t) << 8) + ct);
                #pragma unroll
                for (int j = 0; j < 16; j++) {
                    float4 v = er[j];
                    float* d = es + (4 * j) * ES_STRIDE + t;
                    d[0]             = v.x;
                    d[ES_STRIDE]     = v.y;
                    d[2 * ES_STRIDE] = v.z;
                    d[3 * ES_STRIDE] = v.w;
                }
            }
            __syncthreads();
            // ---- compute: 8px x 8codes per thread, f32x2 packed FMAs,
            // sequential ascending c accumulation.
            #pragma unroll 4
            for (int c = 0; c < 64; c++) {
                const float* zr = zs + c * ZS_STRIDE;
                const float* er = es + c * ES_STRIDE + k0;
                ulonglong2 za = *(const ulonglong2*)(zr + pxA);
                ulonglong2 zb = *(const ulonglong2*)(zr + pxB);
                float4 ea = *(const float4*)(er);
                float4 eb = *(const float4*)(er + 4);
                float ef[8] = {ea.x, ea.y, ea.z, ea.w, eb.x, eb.y, eb.z, eb.w};
                #pragma unroll
                for (int k = 0; k < 8; k++) {
                    u64 ed;
                    asm("mov.b64 %0, {%1, %1};" : "=l"(ed) : "f"(ef[k]));
                    asm("fma.rn.f32x2 %0, %1, %2, %0;" : "+l"(acc[0][k]) : "l"(za.x), "l"(ed));
                    asm("fma.rn.f32x2 %0, %1, %2, %0;" : "+l"(acc[1][k]) : "l"(za.y), "l"(ed));
                    asm("fma.rn.f32x2 %0, %1, %2, %0;" : "+l"(acc[2][k]) : "l"(zb.x), "l"(ed));
                    asm("fma.rn.f32x2 %0, %1, %2, %0;" : "+l"(acc[3][k]) : "l"(zb.y), "l"(ed));
                }
            }
        }
        // ---- fold with the reference's exact fp32 rounding:
        // d = fl( fl(zn2 + en2) - fl(2*dot) );  ascending code order, strict <
        #pragma unroll
        for (int k = 0; k < 8; k++) {
            int code = kb + k0 + k;
            float e2 = g_en2[code];
            #pragma unroll
            for (int pp = 0; pp < 4; pp++) {
                float lo, hi;
                asm("mov.b64 {%0, %1}, %2;" : "=f"(lo), "=f"(hi) : "l"(acc[pp][k]));
                int j = pp * 2;
                float s0 = __fadd_rn(zn2p[j],     e2);
                float s1 = __fadd_rn(zn2p[j + 1], e2);
                float v0 = __fadd_rn(s0, __fmul_rn(-2.0f, lo));
                float v1 = __fadd_rn(s1, __fmul_rn(-2.0f, hi));
                if (v0 < bestv[j])     { bestv[j]     = v0; besti[j]     = code; }
                if (v1 < bestv[j + 1]) { bestv[j + 1] = v1; besti[j + 1] = code; }
            }
        }
    }

    // ---- cross-thread (kg) reduction per pixel; tie -> lowest index
    __syncthreads();
    float* redv = smem;                    // [32][64]
    int*   redi = (int*)(smem + 2048);     // [32][64]
    #pragma unroll
    for (int j = 0; j < 8; j++) {
        int px = (j < 4) ? (pxA + j) : (pxB + j - 4);
        redv[kg * 64 + px] = bestv[j];
        redi[kg * 64 + px] = besti[j];
    }
    __syncthreads();
    if (t < 64) {
        float bv = redv[t];
        int   bi = redi[t];
        #pragma unroll 4
        for (int g = 1; g < 32; g++) {
            float v = redv[g * 64 + t];
            int   i = redi[g * 64 + t];
            if (v < bv || (v == bv && i < bi)) { bv = v; bi = i; }
        }
        int n = blk * 64 + t;
        g_idx[n] = bi;
        out_idx_f[n] = (float)bi;
    }
}

// ---------------------------------------------------------------------------
// Kernel 3: gather z_q, straight-through output (bit-exact z + (z_q - z)),
// partial loss sums.
// ---------------------------------------------------------------------------
__global__ void vq_gather(const float* __restrict__ z, const float* __restrict__ emb,
                          float* __restrict__ outz) {
    int g = blockIdx.x * 256 + threadIdx.x;        // 0 .. 2097151
    long e0 = (long)g * 4;
    int hw = (int)(e0 & 1023);
    int bc = (int)(e0 >> 10);
    int c  = bc & 255;
    int bb = bc >> 8;
    int n  = bb * HWQ + hw;

    int4   id4 = *(const int4*)(g_idx + n);
    float4 zv  = *(const float4*)(z + e0);
    float q0 = __ldg(emb + (long)id4.x * CQ + c);
    float q1 = __ldg(emb + (long)id4.y * CQ + c);
    float q2 = __ldg(emb + (long)id4.z * CQ + c);
    float q3 = __ldg(emb + (long)id4.w * CQ + c);

    float t0 = __fadd_rn(q0, -zv.x), t1 = __fadd_rn(q1, -zv.y);
    float t2 = __fadd_rn(q2, -zv.z), t3 = __fadd_rn(q3, -zv.w);
    float4 o;
    o.x = __fadd_rn(zv.x, t0); o.y = __fadd_rn(zv.y, t1);
    o.z = __fadd_rn(zv.z, t2); o.w = __fadd_rn(zv.w, t3);   // == z + sg(z_q - z)
    *(float4*)(outz + e0) = o;

    float s = fmaf(t0, t0, fmaf(t1, t1, fmaf(t2, t2, t3 * t3)));
    #pragma unroll
    for (int off = 16; off; off >>= 1)
        s += __shfl_xor_sync(0xffffffffu, s, off);
    __shared__ float ws[8];
    if ((threadIdx.x & 31) == 0) ws[threadIdx.x >> 5] = s;
    __syncthreads();
    if (threadIdx.x == 0) {
        float tot = 0.0f;
        #pragma unroll
        for (int i = 0; i < 8; i++) tot += ws[i];
        g_part[blockIdx.x] = tot;
    }
}

// ---------------------------------------------------------------------------
// Kernel 4: deterministic final loss reduction (double accumulation).
// loss = BETA*mean(d^2) + mean(d^2)
// ---------------------------------------------------------------------------
__global__ void vq_loss(float* __restrict__ out) {
    __shared__ double red[256];
    double s = 0.0;
    for (int i = threadIdx.x; i < 8192; i += 256) s += (double)g_part[i];
    red[threadIdx.x] = s;
    __syncthreads();
    for (int st = 128; st; st >>= 1) {
        if (threadIdx.x < st) red[threadIdx.x] += red[threadIdx.x + st];
        __syncthreads();
    }
    if (threadIdx.x == 0) {
        float m = (float)(red[0] / 8388608.0);
        out[ZQ_ELEMS + NPX] = 0.25f * m + m;
    }
}

// ---------------------------------------------------------------------------
extern "C" void kernel_launch(void* const* d_in, const int* in_sizes, int n_in,
                              void* d_out, int out_size) {
    const float* z   = (const float*)d_in[0];
    const float* emb = (const float*)d_in[1];
    float* out = (float*)d_out;

    cudaFuncSetAttribute(vq_argmin, cudaFuncAttributeMaxDynamicSharedMemorySize,
                         SMEM_BYTES);

    vq_en2<<<8, 256>>>(emb);
    vq_zn2<<<4096, 256>>>(z);
    vq_argmin<<<512, 256, SMEM_BYTES>>>(z, emb, out + ZQ_ELEMS);
    vq_gather<<<8192, 256>>>(z, emb, out);
    vq_loss<<<1, 256>>>(out);
}

// round 8
// speedup vs baseline: 1.2032x; 1.2032x over previous
#include <cuda_runtime.h>
#include <cuda_bf16.h>
#include <cstdint>

// Problem constants
// z:   [32, 256, 32, 32] float32   (B, C, H, W)
// emb: [1024, 256] float32         (K, C)
// out: [8388608 z_q_st][32768 indices-as-f32][1 loss]  (float32)

#define BQ      32
#define CQ      256
#define HWQ     1024          // H*W
#define NPX     32768         // B*H*W
#define KQ      1024
#define ZQ_ELEMS 8388608      // B*C*H*W

typedef unsigned long long u64;

// Scratch (no allocations allowed)
__device__ float g_en2[KQ];
__device__ int   g_idx[NPX];
__device__ float g_part[8192];

// ---------------------------------------------------------------------------
// Kernel 1: ||e_k||^2 per code (mag ~8e-5: order noise invisible on the
// fl(zn2+en2) grid at ~256).
// ---------------------------------------------------------------------------
__global__ void vq_en2(const float* __restrict__ emb) {
    int warp = (blockIdx.x * blockDim.x + threadIdx.x) >> 5;   // 0..63
    int lane = threadIdx.x & 31;
    for (int i = 0; i < 16; i++) {
        int k = warp * 16 + i;
        const float* row = emb + (long)k * CQ;
        float s = 0.0f;
        #pragma unroll
        for (int j = 0; j < 8; j++) {
            float v = row[lane + 32 * j];
            s = __fadd_rn(s, __fmul_rn(v, v));
        }
        #pragma unroll
        for (int off = 16; off; off >>= 1)
            s = __fadd_rn(s, __shfl_xor_sync(0xffffffffu, s, off));
        if (lane == 0) g_en2[k] = s;
    }
}

// ---------------------------------------------------------------------------
// Kernel 2: fused distance-GEMM + argmin, cp.async ping-pong pipeline.
//  - 32 stages = 4 kb-blocks x 8 c-halftiles of 32 channels.
//  - z tile [32c x 64px] native c-major (direct copy); e tile [256k x 32c]
//    native k-major (direct copy, row stride 36 floats for bank spread).
//  - thread tile 8px x 8codes (codes kg+32j, ascending in j), f32x2 FMA,
//    dot chain bit-identical to the R6-passing kernel.
//  - ||z||^2 accumulated inline during kb=0 (argmin-invariant ordering).
//  - distance fold replicates reference fp32 rounding:
//      d = fl( fl(zn2 + en2) - fl(2*dot) ); ties -> lowest index.
// ---------------------------------------------------------------------------
#define ZS0 0
#define ZS1 2048
#define ES0 4096
#define ESB 9216          // 256 * 36
#define SMEM_FLOATS 22528 // ZS 2*2048 + ES 2*9216
#define SMEM_BYTES (SMEM_FLOATS * 4)   // 90112

__device__ __forceinline__ void cpasync16(uint32_t dst, const void* src) {
    asm volatile("cp.async.cg.shared.global [%0], [%1], 16;" :: "r"(dst), "l"(src));
}

__device__ __forceinline__ void fill_stage(uint32_t sm32, const float* zbase,
                                           const float* emb, int s, int b, int t) {
    int kb = (s >> 3) << 8;      // code block base
    int cb = (s & 7) << 5;       // channel base
    // z: 32 rows x 64 floats = 512 16B-chunks
    #pragma unroll
    for (int i = 0; i < 2; i++) {
        int idx = t + (i << 8);
        int cl = idx >> 4;
        int q  = (idx & 15) << 2;
        const float* src = zbase + (long)(cb + cl) * HWQ + q;
        uint32_t dst = sm32 + (uint32_t)(((b ? ZS1 : ZS0) + cl * 64 + q) << 2);
        cpasync16(dst, src);
    }
    // e: 256 rows x 32 floats = 2048 16B-chunks
    #pragma unroll
    for (int i = 0; i < 8; i++) {
        int idx = t + (i << 8);
        int k = idx >> 3;
        int q = (idx & 7) << 2;
        const float* src = emb + (long)(kb + k) * CQ + cb + q;
        uint32_t dst = sm32 + (uint32_t)((ES0 + b * ESB + k * 36 + q) << 2);
        cpasync16(dst, src);
    }
}

template <bool ZSQ>
__device__ __forceinline__ void compute_stage(const float* __restrict__ zsp,
                                              const float* __restrict__ ep0,
                                              int pxA, int pxB,
                                              u64 acc[4][8], u64 zsq[4]) {
    #pragma unroll 4
    for (int c = 0; c < 32; c++) {
        const float* zr = zsp + c * 64;
        ulonglong2 za = *(const ulonglong2*)(zr + pxA);  // (pxA,pxA+1),(pxA+2,pxA+3)
        ulonglong2 zb = *(const ulonglong2*)(zr + pxB);
        float ef[8];
        #pragma unroll
        for (int j = 0; j < 8; j++) ef[j] = ep0[j * (32 * 36) + c];
        if (ZSQ) {
            asm("fma.rn.f32x2 %0, %1, %1, %0;" : "+l"(zsq[0]) : "l"(za.x));
            asm("fma.rn.f32x2 %0, %1, %1, %0;" : "+l"(zsq[1]) : "l"(za.y));
            asm("fma.rn.f32x2 %0, %1, %1, %0;" : "+l"(zsq[2]) : "l"(zb.x));
            asm("fma.rn.f32x2 %0, %1, %1, %0;" : "+l"(zsq[3]) : "l"(zb.y));
        }
        #pragma unroll
        for (int j = 0; j < 8; j++) {
            u64 ed;
            asm("mov.b64 %0, {%1, %1};" : "=l"(ed) : "f"(ef[j]));
            asm("fma.rn.f32x2 %0, %1, %2, %0;" : "+l"(acc[0][j]) : "l"(za.x), "l"(ed));
            asm("fma.rn.f32x2 %0, %1, %2, %0;" : "+l"(acc[1][j]) : "l"(za.y), "l"(ed));
            asm("fma.rn.f32x2 %0, %1, %2, %0;" : "+l"(acc[2][j]) : "l"(zb.x), "l"(ed));
            asm("fma.rn.f32x2 %0, %1, %2, %0;" : "+l"(acc[3][j]) : "l"(zb.y), "l"(ed));
        }
    }
}

__global__ void __launch_bounds__(256, 2)
vq_argmin(const float* __restrict__ z, const float* __restrict__ emb,
          float* __restrict__ out_idx_f) {
    extern __shared__ float smem[];
    uint32_t sm32 = (uint32_t)__cvta_generic_to_shared(smem);

    const int t  = threadIdx.x;
    const int pg = t & 7;          // pixel group
    const int kg = t >> 3;         // code group (0..31)
    const int blk = blockIdx.x;
    const int bb  = blk >> 4;
    const int hw0 = (blk & 15) << 6;
    const float* zbase = z + ((long)bb << 18) + hw0;

    const int pxA = pg * 4;
    const int pxB = 32 + pg * 4;

    float bestv[8];
    int   besti[8];
    #pragma unroll
    for (int i = 0; i < 8; i++) { bestv[i] = 3.402823466e38f; besti[i] = 0x7fffffff; }
    float zn2p[8];
    u64 zsq[4] = {0ull, 0ull, 0ull, 0ull};
    u64 acc[4][8];

    // prologue: fill stage 0
    fill_stage(sm32, zbase, emb, 0, 0, t);
    asm volatile("cp.async.commit_group;" ::: "memory");

    for (int s = 0; s < 32; s++) {
        if ((s & 7) == 0) {
            #pragma unroll
            for (int pp = 0; pp < 4; pp++)
                #pragma unroll
                for (int j = 0; j < 8; j++) acc[pp][j] = 0ull;
        }
        asm volatile("cp.async.wait_group 0;" ::: "memory");
        __syncthreads();
        if (s < 31) {
            fill_stage(sm32, zbase, emb, s + 1, (s + 1) & 1, t);
            asm volatile("cp.async.commit_group;" ::: "memory");
        }
        const int b = s & 1;
        const float* zsp = smem + (b ? ZS1 : ZS0);
        const float* ep0 = smem + ES0 + b * ESB + kg * 36;
        if (s < 8) compute_stage<true >(zsp, ep0, pxA, pxB, acc, zsq);
        else       compute_stage<false>(zsp, ep0, pxA, pxB, acc, zsq);

        if ((s & 7) == 7) {
            int kb = (s >> 3) << 8;
            if (s == 7) {
                // unpack per-pixel ||z||^2 (full sequential-c fma chains)
                #pragma unroll
                for (int pp = 0; pp < 4; pp++) {
                    float lo, hi;
                    asm("mov.b64 {%0, %1}, %2;" : "=f"(lo), "=f"(hi) : "l"(zsq[pp]));
                    zn2p[pp * 2] = lo; zn2p[pp * 2 + 1] = hi;
                }
            }
            // fold: codes kb + kg + 32*j, ascending j; reference fp32 rounding
            #pragma unroll
            for (int j = 0; j < 8; j++) {
                int code = kb + kg + 32 * j;
                float e2 = g_en2[code];
                #pragma unroll
                for (int pp = 0; pp < 4; pp++) {
                    float lo, hi;
                    asm("mov.b64 {%0, %1}, %2;" : "=f"(lo), "=f"(hi) : "l"(acc[pp][j]));
                    int i2 = pp * 2;
                    float s0 = __fadd_rn(zn2p[i2],     e2);
                    float s1 = __fadd_rn(zn2p[i2 + 1], e2);
                    float v0 = __fadd_rn(s0, __fmul_rn(-2.0f, lo));
                    float v1 = __fadd_rn(s1, __fmul_rn(-2.0f, hi));
                    if (v0 < bestv[i2])     { bestv[i2]     = v0; besti[i2]     = code; }
                    if (v1 < bestv[i2 + 1]) { bestv[i2 + 1] = v1; besti[i2 + 1] = code; }
                }
            }
        }
    }

    // ---- cross-thread (kg) reduction per pixel; tie -> lowest index
    __syncthreads();
    float* redv = smem;                    // [32][64]
    int*   redi = (int*)(smem + 2048);     // [32][64]
    #pragma unroll
    for (int j = 0; j < 8; j++) {
        int px = (j < 4) ? (pxA + j) : (pxB + j - 4);
        redv[kg * 64 + px] = bestv[j];
        redi[kg * 64 + px] = besti[j];
    }
    __syncthreads();
    if (t < 64) {
        float bv = redv[t];
        int   bi = redi[t];
        #pragma unroll 4
        for (int g = 1; g < 32; g++) {
            float v = redv[g * 64 + t];
            int   i = redi[g * 64 + t];
            if (v < bv || (v == bv && i < bi)) { bv = v; bi = i; }
        }
        int n = blk * 64 + t;
        g_idx[n] = bi;
        out_idx_f[n] = (float)bi;
    }
}

// ---------------------------------------------------------------------------
// Kernel 3: gather z_q, straight-through output (bit-exact z + (z_q - z)),
// partial loss sums.
// ---------------------------------------------------------------------------
__global__ void vq_gather(const float* __restrict__ z, const float* __restrict__ emb,
                          float* __restrict__ outz) {
    int g = blockIdx.x * 256 + threadIdx.x;        // 0 .. 2097151
    long e0 = (long)g * 4;
    int hw = (int)(e0 & 1023);
    int bc = (int)(e0 >> 10);
    int c  = bc & 255;
    int bb = bc >> 8;
    int n  = bb * HWQ + hw;

    int4   id4 = *(const int4*)(g_idx + n);
    float4 zv  = *(const float4*)(z + e0);
    float q0 = __ldg(emb + (long)id4.x * CQ + c);
    float q1 = __ldg(emb + (long)id4.y * CQ + c);
    float q2 = __ldg(emb + (long)id4.z * CQ + c);
    float q3 = __ldg(emb + (long)id4.w * CQ + c);

    float t0 = __fadd_rn(q0, -zv.x), t1 = __fadd_rn(q1, -zv.y);
    float t2 = __fadd_rn(q2, -zv.z), t3 = __fadd_rn(q3, -zv.w);
    float4 o;
    o.x = __fadd_rn(zv.x, t0); o.y = __fadd_rn(zv.y, t1);
    o.z = __fadd_rn(zv.z, t2); o.w = __fadd_rn(zv.w, t3);   // == z + sg(z_q - z)
    *(float4*)(outz + e0) = o;

    float s = fmaf(t0, t0, fmaf(t1, t1, fmaf(t2, t2, t3 * t3)));
    #pragma unroll
    for (int off = 16; off; off >>= 1)
        s += __shfl_xor_sync(0xffffffffu, s, off);
    __shared__ float ws[8];
    if ((threadIdx.x & 31) == 0) ws[threadIdx.x >> 5] = s;
    __syncthreads();
    if (threadIdx.x == 0) {
        float tot = 0.0f;
        #pragma unroll
        for (int i = 0; i < 8; i++) tot += ws[i];
        g_part[blockIdx.x] = tot;
    }
}

// ---------------------------------------------------------------------------
// Kernel 4: deterministic final loss reduction (double accumulation).
// ---------------------------------------------------------------------------
__global__ void vq_loss(float* __restrict__ out) {
    __shared__ double red[256];
    double s = 0.0;
    for (int i = threadIdx.x; i < 8192; i += 256) s += (double)g_part[i];
    red[threadIdx.x] = s;
    __syncthreads();
    for (int st = 128; st; st >>= 1) {
        if (threadIdx.x < st) red[threadIdx.x] += red[threadIdx.x + st];
        __syncthreads();
    }
    if (threadIdx.x == 0) {
        float m = (float)(red[0] / 8388608.0);
        out[ZQ_ELEMS + NPX] = 0.25f * m + m;
    }
}

// ---------------------------------------------------------------------------
extern "C" void kernel_launch(void* const* d_in, const int* in_sizes, int n_in,
                              void* d_out, int out_size) {
    const float* z   = (const float*)d_in[0];
    const float* emb = (const float*)d_in[1];
    float* out = (float*)d_out;

    cudaFuncSetAttribute(vq_argmin, cudaFuncAttributeMaxDynamicSharedMemorySize,
                         SMEM_BYTES);

    vq_en2<<<8, 256>>>(emb);
    vq_argmin<<<512, 256, SMEM_BYTES>>>(z, emb, out + ZQ_ELEMS);
    vq_gather<<<8192, 256>>>(z, emb, out);
    vq_loss<<<1, 256>>>(out);
}